// round 7
// baseline (speedup 1.0000x reference)
#include <cuda_runtime.h>
#include <cuda_bf16.h>
#include <cstdint>

// Problem constants (fixed shapes per reference)
#define NN 100000      // nodes
#define EE 1600000     // edges (without self loops)
#define HD 128         // feature / hidden dim
#define OD 40          // out dim

// Persistent scratch (no cudaMalloc allowed).
// RULE: these symbols are ONLY referenced from device code. Passing them as
// kernel arguments from host code yields the host shadow address (silently
// "works" on GB300 via ATS but reads/writes the wrong memory).
__device__ float g_h[(size_t)NN * HD];     // X @ W (pre-aggregation)
__device__ float g_agg[(size_t)NN * HD];   // scatter-add target
__device__ float g_out1[(size_t)NN * HD];  // relu(layer1)  (kept for residual)
__device__ float g_out2[(size_t)NN * HD];  // relu(layer2)
__device__ float g_deg[NN];
__device__ float g_dinv[NN];

// ---------------------------------------------------------------------------
// degree / dinv
// ---------------------------------------------------------------------------
__global__ void init_deg_kernel(int n) {
    int i = blockIdx.x * blockDim.x + threadIdx.x;
    if (i < n) g_deg[i] = 1.0f;  // self loop
}

__global__ void count_deg_kernel(const int* __restrict__ dst, int nE) {
    int i = blockIdx.x * blockDim.x + threadIdx.x;
    if (i < nE) atomicAdd(&g_deg[dst[i]], 1.0f);
}

__global__ void dinv_kernel(int n) {
    int i = blockIdx.x * blockDim.x + threadIdx.x;
    if (i < n) g_dinv[i] = rsqrtf(g_deg[i]);
}

// ---------------------------------------------------------------------------
// zero g_agg (float4)
// ---------------------------------------------------------------------------
__global__ void zero_agg_kernel(int n4) {
    int i = blockIdx.x * blockDim.x + threadIdx.x;
    if (i < n4) ((float4*)g_agg)[i] = make_float4(0.f, 0.f, 0.f, 0.f);
}

// ---------------------------------------------------------------------------
// GEMM: g_h[n,128] = A[n,128] @ W[128,128]
// srcsel == 0 : A = Aext (harness input x, a real device pointer)
// srcsel == 1 : A = g_out1 (device symbol, resolved in device code)
// 256 threads: 64 rows x (4 groups of 32 cols). Lanes within a warp share the
// same column group -> SMEM W reads are pure broadcast (conflict free).
// W staged in two 64-row K-halves (32KB static smem).
// ---------------------------------------------------------------------------
__global__ __launch_bounds__(256) void gemm128_kernel(
    const float* __restrict__ Aext, const float* __restrict__ W,
    int srcsel, int nrows)
{
    __shared__ float Ws[64 * 128];
    const float* A = srcsel ? (const float*)g_out1 : Aext;

    int tid = threadIdx.x;
    int row = blockIdx.x * 64 + (tid & 63);
    int c0  = (tid >> 6) * 32;

    float acc[32];
#pragma unroll
    for (int j = 0; j < 32; j++) acc[j] = 0.f;

    bool valid = row < nrows;
    const float* Arow = A + (size_t)row * HD;

#pragma unroll
    for (int kh = 0; kh < 2; kh++) {
        __syncthreads();
        const float4* Wg  = (const float4*)(W + kh * 64 * 128);
        float4*       Wsm = (float4*)Ws;
#pragma unroll
        for (int i = 0; i < 8; i++) Wsm[tid + i * 256] = Wg[tid + i * 256];
        __syncthreads();

        if (valid) {
#pragma unroll 2
            for (int k4 = 0; k4 < 16; k4++) {
                float4 a = *(const float4*)(Arow + kh * 64 + k4 * 4);
                float av[4] = {a.x, a.y, a.z, a.w};
#pragma unroll
                for (int kk = 0; kk < 4; kk++) {
                    const float* wrow = Ws + (k4 * 4 + kk) * 128 + c0;
#pragma unroll
                    for (int j = 0; j < 32; j++) acc[j] += av[kk] * wrow[j];
                }
            }
        }
    }

    if (valid) {
        float* Crow = g_h + (size_t)row * HD + c0;
#pragma unroll
        for (int j = 0; j < 32; j += 4)
            *(float4*)(Crow + j) = make_float4(acc[j], acc[j+1], acc[j+2], acc[j+3]);
    }
}

// ---------------------------------------------------------------------------
// Edge aggregation: one warp per edge.
//   g_agg[dst] += g_h[src] * dinv[src] * dinv[dst]
// ---------------------------------------------------------------------------
__global__ __launch_bounds__(256) void aggregate_kernel(
    const int* __restrict__ src, const int* __restrict__ dst, int nE)
{
    int widx = (blockIdx.x * blockDim.x + threadIdx.x) >> 5;
    int lane = threadIdx.x & 31;
    if (widx >= nE) return;

    int s = __ldg(&src[widx]);
    int d = __ldg(&dst[widx]);
    float norm = g_dinv[s] * g_dinv[d];

    float4 v = *(const float4*)(g_h + (size_t)s * HD + lane * 4);
    float* p = g_agg + (size_t)d * HD + lane * 4;
    atomicAdd(p + 0, v.x * norm);
    atomicAdd(p + 1, v.y * norm);
    atomicAdd(p + 2, v.z * norm);
    atomicAdd(p + 3, v.w * norm);
}

// ---------------------------------------------------------------------------
// Epilogue: out = relu(agg + h * dinv^2 + b)   (self-loop fused in)
// dstsel == 0 -> g_out1,  dstsel == 1 -> g_out2
// One thread per float4.
// ---------------------------------------------------------------------------
__global__ void epilogue_kernel(const float* __restrict__ b,
                                int dstsel, int n4)
{
    int i = blockIdx.x * blockDim.x + threadIdx.x;
    if (i >= n4) return;                 // n4 = N * 32
    float* outbuf = dstsel ? (float*)g_out2 : (float*)g_out1;
    int node = i >> 5;                   // 32 float4 per node
    int f4   = i & 31;
    float di = g_dinv[node];
    float sl = di * di;
    float4 ag = ((const float4*)g_agg)[i];
    float4 hv = ((const float4*)g_h)[i];
    const float* bp = b + f4 * 4;
    float4 r;
    r.x = fmaxf(ag.x + hv.x * sl + bp[0], 0.f);
    r.y = fmaxf(ag.y + hv.y * sl + bp[1], 0.f);
    r.z = fmaxf(ag.z + hv.z * sl + bp[2], 0.f);
    r.w = fmaxf(ag.w + hv.w * sl + bp[3], 0.f);
    ((float4*)outbuf)[i] = r;
}

// ---------------------------------------------------------------------------
// Classifier: out[n,40] = (g_out1 + g_out2)[n,128] @ Wc[128,40] + bc
// One thread per row; Wc staged in SMEM (broadcast reads).
// ---------------------------------------------------------------------------
__global__ __launch_bounds__(256) void classifier_kernel(
    const float* __restrict__ Wc, const float* __restrict__ bc,
    float* __restrict__ out, int nrows)
{
    __shared__ float Ws[128 * OD];
    int tid = threadIdx.x;
    for (int i = tid; i < 128 * OD; i += 256) Ws[i] = Wc[i];
    __syncthreads();

    int row = blockIdx.x * 256 + tid;
    if (row >= nrows) return;

    float acc[OD];
#pragma unroll
    for (int j = 0; j < OD; j++) acc[j] = bc[j];

    const float* p1 = g_out1 + (size_t)row * HD;
    const float* p2 = g_out2 + (size_t)row * HD;

#pragma unroll 2
    for (int k4 = 0; k4 < 32; k4++) {
        float4 a1 = *(const float4*)(p1 + 4 * k4);
        float4 a2 = *(const float4*)(p2 + 4 * k4);
        float av[4] = {a1.x + a2.x, a1.y + a2.y, a1.z + a2.z, a1.w + a2.w};
#pragma unroll
        for (int kk = 0; kk < 4; kk++) {
            const float* wrow = Ws + (k4 * 4 + kk) * OD;
#pragma unroll
            for (int j = 0; j < OD; j++) acc[j] += av[kk] * wrow[j];
        }
    }

    float* orow = out + (size_t)row * OD;
#pragma unroll
    for (int j = 0; j < OD; j += 4)
        *(float4*)(orow + j) = make_float4(acc[j], acc[j+1], acc[j+2], acc[j+3]);
}

// ---------------------------------------------------------------------------
extern "C" void kernel_launch(void* const* d_in, const int* in_sizes, int n_in,
                              void* d_out, int out_size)
{
    const float* x  = (const float*)d_in[0];
    const float* W1 = (const float*)d_in[1];
    const float* b1 = (const float*)d_in[2];
    const float* W2 = (const float*)d_in[3];
    const float* b2 = (const float*)d_in[4];
    const float* Wc = (const float*)d_in[5];
    const float* bc = (const float*)d_in[6];
    const int*   ei = (const int*)d_in[7];

    const int n  = in_sizes[0] / HD;     // 100000
    const int nE = in_sizes[7] / 2;      // 1600000
    const int* src = ei;
    const int* dst = ei + nE;

    const int n4 = n * (HD / 4);         // float4 count per node buffer

    // degree + dinv (recomputed every call; deterministic result)
    init_deg_kernel<<<(n + 255) / 256, 256>>>(n);
    count_deg_kernel<<<(nE + 255) / 256, 256>>>(dst, nE);
    dinv_kernel<<<(n + 255) / 256, 256>>>(n);

    // ---- layer 1 ----
    gemm128_kernel<<<(n + 63) / 64, 256>>>(x, W1, /*srcsel=*/0, n);
    zero_agg_kernel<<<(n4 + 255) / 256, 256>>>(n4);
    aggregate_kernel<<<(nE * 32 + 255) / 256, 256>>>(src, dst, nE);
    epilogue_kernel<<<(n4 + 255) / 256, 256>>>(b1, /*dstsel=*/0, n4);

    // ---- layer 2 ----
    gemm128_kernel<<<(n + 63) / 64, 256>>>(x /*unused*/, W2, /*srcsel=*/1, n);
    zero_agg_kernel<<<(n4 + 255) / 256, 256>>>(n4);
    aggregate_kernel<<<(nE * 32 + 255) / 256, 256>>>(src, dst, nE);
    epilogue_kernel<<<(n4 + 255) / 256, 256>>>(b2, /*dstsel=*/1, n4);

    // ---- classifier with fused residual ----
    classifier_kernel<<<(n + 255) / 256, 256>>>(Wc, bc, (float*)d_out, n);
}

// round 8
// speedup vs baseline: 1.0031x; 1.0031x over previous
#include <cuda_runtime.h>
#include <cuda_bf16.h>
#include <cstdint>

// Problem constants (fixed shapes per reference)
#define NN 100000      // nodes
#define EE 1600000     // edges (without self loops)
#define HD 128         // feature / hidden dim
#define OD 40          // out dim

// Persistent scratch (no cudaMalloc allowed).
// RULE: these symbols are ONLY referenced from device code. Passing them as
// kernel arguments from host code yields the host shadow address (silently
// "works" on GB300 via ATS but reads/writes the wrong memory).
__device__ float g_h[(size_t)NN * HD];     // X @ W (pre-aggregation)
__device__ float g_agg[(size_t)NN * HD];   // scatter-add target
__device__ float g_out1[(size_t)NN * HD];  // relu(layer1)  (kept for residual)
__device__ float g_out2[(size_t)NN * HD];  // relu(layer2)
__device__ float g_deg[NN];
__device__ float g_dinv[NN];

// ---------------------------------------------------------------------------
// degree / dinv
// ---------------------------------------------------------------------------
__global__ void init_deg_kernel(int n) {
    int i = blockIdx.x * blockDim.x + threadIdx.x;
    if (i < n) g_deg[i] = 1.0f;  // self loop
}

__global__ void count_deg_kernel(const int* __restrict__ dst, int nE) {
    int i = blockIdx.x * blockDim.x + threadIdx.x;
    if (i < nE) atomicAdd(&g_deg[dst[i]], 1.0f);
}

__global__ void dinv_kernel(int n) {
    int i = blockIdx.x * blockDim.x + threadIdx.x;
    if (i < n) g_dinv[i] = rsqrtf(g_deg[i]);
}

// ---------------------------------------------------------------------------
// zero g_agg (float4)
// ---------------------------------------------------------------------------
__global__ void zero_agg_kernel(int n4) {
    int i = blockIdx.x * blockDim.x + threadIdx.x;
    if (i < n4) ((float4*)g_agg)[i] = make_float4(0.f, 0.f, 0.f, 0.f);
}

// ---------------------------------------------------------------------------
// GEMM: g_h[n,128] = A[n,128] @ W[128,128]
// srcsel == 0 : A = Aext (harness input x, a real device pointer)
// srcsel == 1 : A = g_out1 (device symbol, resolved in device code)
// 256 threads: 64 rows x (4 groups of 32 cols). Lanes within a warp share the
// same column group -> SMEM W reads are pure broadcast (conflict free).
// W staged in two 64-row K-halves (32KB static smem).
// ---------------------------------------------------------------------------
__global__ __launch_bounds__(256) void gemm128_kernel(
    const float* __restrict__ Aext, const float* __restrict__ W,
    int srcsel, int nrows)
{
    __shared__ float Ws[64 * 128];
    const float* A = srcsel ? (const float*)g_out1 : Aext;

    int tid = threadIdx.x;
    int row = blockIdx.x * 64 + (tid & 63);
    int c0  = (tid >> 6) * 32;

    float acc[32];
#pragma unroll
    for (int j = 0; j < 32; j++) acc[j] = 0.f;

    bool valid = row < nrows;
    const float* Arow = A + (size_t)row * HD;

#pragma unroll
    for (int kh = 0; kh < 2; kh++) {
        __syncthreads();
        const float4* Wg  = (const float4*)(W + kh * 64 * 128);
        float4*       Wsm = (float4*)Ws;
#pragma unroll
        for (int i = 0; i < 8; i++) Wsm[tid + i * 256] = Wg[tid + i * 256];
        __syncthreads();

        if (valid) {
#pragma unroll 2
            for (int k4 = 0; k4 < 16; k4++) {
                float4 a = *(const float4*)(Arow + kh * 64 + k4 * 4);
                float av[4] = {a.x, a.y, a.z, a.w};
#pragma unroll
                for (int kk = 0; kk < 4; kk++) {
                    const float* wrow = Ws + (k4 * 4 + kk) * 128 + c0;
#pragma unroll
                    for (int j = 0; j < 32; j++) acc[j] += av[kk] * wrow[j];
                }
            }
        }
    }

    if (valid) {
        float* Crow = g_h + (size_t)row * HD + c0;
#pragma unroll
        for (int j = 0; j < 32; j += 4)
            *(float4*)(Crow + j) = make_float4(acc[j], acc[j+1], acc[j+2], acc[j+3]);
    }
}

// ---------------------------------------------------------------------------
// Edge aggregation: one warp per edge.
//   g_agg[dst] += g_h[src] * dinv[src] * dinv[dst]
// ---------------------------------------------------------------------------
__global__ __launch_bounds__(256) void aggregate_kernel(
    const int* __restrict__ src, const int* __restrict__ dst, int nE)
{
    int widx = (blockIdx.x * blockDim.x + threadIdx.x) >> 5;
    int lane = threadIdx.x & 31;
    if (widx >= nE) return;

    int s = __ldg(&src[widx]);
    int d = __ldg(&dst[widx]);
    float norm = g_dinv[s] * g_dinv[d];

    float4 v = *(const float4*)(g_h + (size_t)s * HD + lane * 4);
    float* p = g_agg + (size_t)d * HD + lane * 4;
    atomicAdd(p + 0, v.x * norm);
    atomicAdd(p + 1, v.y * norm);
    atomicAdd(p + 2, v.z * norm);
    atomicAdd(p + 3, v.w * norm);
}

// ---------------------------------------------------------------------------
// Epilogue: out = relu(agg + h * dinv^2 + b)   (self-loop fused in)
// dstsel == 0 -> g_out1,  dstsel == 1 -> g_out2
// One thread per float4.
// ---------------------------------------------------------------------------
__global__ void epilogue_kernel(const float* __restrict__ b,
                                int dstsel, int n4)
{
    int i = blockIdx.x * blockDim.x + threadIdx.x;
    if (i >= n4) return;                 // n4 = N * 32
    float* outbuf = dstsel ? (float*)g_out2 : (float*)g_out1;
    int node = i >> 5;                   // 32 float4 per node
    int f4   = i & 31;
    float di = g_dinv[node];
    float sl = di * di;
    float4 ag = ((const float4*)g_agg)[i];
    float4 hv = ((const float4*)g_h)[i];
    const float* bp = b + f4 * 4;
    float4 r;
    r.x = fmaxf(ag.x + hv.x * sl + bp[0], 0.f);
    r.y = fmaxf(ag.y + hv.y * sl + bp[1], 0.f);
    r.z = fmaxf(ag.z + hv.z * sl + bp[2], 0.f);
    r.w = fmaxf(ag.w + hv.w * sl + bp[3], 0.f);
    ((float4*)outbuf)[i] = r;
}

// ---------------------------------------------------------------------------
// Classifier: out[n,40] = (g_out1 + g_out2)[n,128] @ Wc[128,40] + bc
// One thread per row; Wc staged in SMEM (broadcast reads).
// ---------------------------------------------------------------------------
__global__ __launch_bounds__(256) void classifier_kernel(
    const float* __restrict__ Wc, const float* __restrict__ bc,
    float* __restrict__ out, int nrows)
{
    __shared__ float Ws[128 * OD];
    int tid = threadIdx.x;
    for (int i = tid; i < 128 * OD; i += 256) Ws[i] = Wc[i];
    __syncthreads();

    int row = blockIdx.x * 256 + tid;
    if (row >= nrows) return;

    float acc[OD];
#pragma unroll
    for (int j = 0; j < OD; j++) acc[j] = bc[j];

    const float* p1 = g_out1 + (size_t)row * HD;
    const float* p2 = g_out2 + (size_t)row * HD;

#pragma unroll 2
    for (int k4 = 0; k4 < 32; k4++) {
        float4 a1 = *(const float4*)(p1 + 4 * k4);
        float4 a2 = *(const float4*)(p2 + 4 * k4);
        float av[4] = {a1.x + a2.x, a1.y + a2.y, a1.z + a2.z, a1.w + a2.w};
#pragma unroll
        for (int kk = 0; kk < 4; kk++) {
            const float* wrow = Ws + (k4 * 4 + kk) * OD;
#pragma unroll
            for (int j = 0; j < OD; j++) acc[j] += av[kk] * wrow[j];
        }
    }

    float* orow = out + (size_t)row * OD;
#pragma unroll
    for (int j = 0; j < OD; j += 4)
        *(float4*)(orow + j) = make_float4(acc[j], acc[j+1], acc[j+2], acc[j+3]);
}

// ---------------------------------------------------------------------------
extern "C" void kernel_launch(void* const* d_in, const int* in_sizes, int n_in,
                              void* d_out, int out_size)
{
    const float* x  = (const float*)d_in[0];
    const float* W1 = (const float*)d_in[1];
    const float* b1 = (const float*)d_in[2];
    const float* W2 = (const float*)d_in[3];
    const float* b2 = (const float*)d_in[4];
    const float* Wc = (const float*)d_in[5];
    const float* bc = (const float*)d_in[6];
    const int*   ei = (const int*)d_in[7];

    const int n  = in_sizes[0] / HD;     // 100000
    const int nE = in_sizes[7] / 2;      // 1600000
    const int* src = ei;
    const int* dst = ei + nE;

    const int n4 = n * (HD / 4);         // float4 count per node buffer

    // degree + dinv (recomputed every call; deterministic result)
    init_deg_kernel<<<(n + 255) / 256, 256>>>(n);
    count_deg_kernel<<<(nE + 255) / 256, 256>>>(dst, nE);
    dinv_kernel<<<(n + 255) / 256, 256>>>(n);

    // ---- layer 1 ----
    gemm128_kernel<<<(n + 63) / 64, 256>>>(x, W1, /*srcsel=*/0, n);
    zero_agg_kernel<<<(n4 + 255) / 256, 256>>>(n4);
    aggregate_kernel<<<(nE * 32 + 255) / 256, 256>>>(src, dst, nE);
    epilogue_kernel<<<(n4 + 255) / 256, 256>>>(b1, /*dstsel=*/0, n4);

    // ---- layer 2 ----
    gemm128_kernel<<<(n + 63) / 64, 256>>>(x /*unused*/, W2, /*srcsel=*/1, n);
    zero_agg_kernel<<<(n4 + 255) / 256, 256>>>(n4);
    aggregate_kernel<<<(nE * 32 + 255) / 256, 256>>>(src, dst, nE);
    epilogue_kernel<<<(n4 + 255) / 256, 256>>>(b2, /*dstsel=*/1, n4);

    // ---- classifier with fused residual ----
    classifier_kernel<<<(n + 255) / 256, 256>>>(Wc, bc, (float*)d_out, n);
}